// round 3
// baseline (speedup 1.0000x reference)
#include <cuda_runtime.h>

// Fixed problem shape
#define BATCH 8
#define CDIM  64
#define NPTS  4096
#define KNN   20
#define TM    128   // targets per block == threads per block
#define TC    64    // candidate tile size

// ---------------------------------------------------------------------------
// One kernel. One thread = one target point.
//  - Target features in registers (64 floats).
//  - Candidate tile (64 pts x 64 ch, channel-major) in SMEM; dot products via
//    uniform float4 broadcast loads (1 LDS.128 per 4 FFMA4).
//  - Exact top-K via packed u64 keys (d2_bits<<32 | idx): u64 '<' implements
//    lax.top_k's (distance asc, lower index first) ordering exactly.
//  - d2 = fma(dot, -2, sq_t + sq_j): identical rounding to the reference's
//    sq[:,:,None] + sq[:,None,:] - 2*einsum.
//  - OUTPUT IS FLOAT32 (harness output dtype): indices written as floats.
// ---------------------------------------------------------------------------
__global__ void __launch_bounds__(TM) knn_all(const float* __restrict__ x,
                                              float* __restrict__ out) {
    __shared__ __align__(16) float sf[CDIM * TC];  // tile, channel-major rows
    __shared__ float s_csq[TC];                    // candidate squared norms

    const int b   = blockIdx.y;
    const int tid = threadIdx.x;
    const int tgt = blockIdx.x * TM + tid;
    const float* xb = x + b * CDIM * NPTS;

    // Target features -> registers; target squared norm.
    float tq[CDIM];
    float sqt = 0.f;
#pragma unroll
    for (int c = 0; c < CDIM; c++) {
        tq[c] = xb[c * NPTS + tgt];
        sqt = fmaf(tq[c], tq[c], sqt);
    }

    // Top-K state: packed keys, sentinel = max u64.
    unsigned long long top[KNN];
#pragma unroll
    for (int k = 0; k < KNN; k++) top[k] = ~0ull;
    unsigned long long curMax = ~0ull;  // largest key currently held
    int curSlot = 0;                    // its slot

    const int cand  = tid & (TC - 1);   // candidate column this thread stages
    const int chalf = tid >> 6;         // channel parity (TM = 2*TC)

    for (int j0 = 0; j0 < NPTS; j0 += TC) {
        __syncthreads();                // prior tile fully consumed
        // Stage candidate tile: thread handles 32 channels of one candidate.
        for (int c = chalf; c < CDIM; c += 2)
            sf[c * TC + cand] = xb[c * NPTS + j0 + cand];
        __syncthreads();
        // Candidate squared norms from the staged tile.
        if (tid < TC) {
            float s = 0.f;
#pragma unroll
            for (int c = 0; c < CDIM; c++) {
                float v = sf[c * TC + tid];
                s = fmaf(v, v, s);
            }
            s_csq[tid] = s;
        }
        __syncthreads();

        for (int jg = 0; jg < TC; jg += 4) {
            float4 acc = make_float4(0.f, 0.f, 0.f, 0.f);
            const float4* row4 = reinterpret_cast<const float4*>(sf) + (jg >> 2);
#pragma unroll
            for (int c = 0; c < CDIM; c++) {
                float4 cv = row4[c * (TC / 4)];   // uniform broadcast LDS.128
                float a = tq[c];
                acc.x = fmaf(a, cv.x, acc.x);
                acc.y = fmaf(a, cv.y, acc.y);
                acc.z = fmaf(a, cv.z, acc.z);
                acc.w = fmaf(a, cv.w, acc.w);
            }
#pragma unroll
            for (int u = 0; u < 4; u++) {
                float dot = (u == 0) ? acc.x : (u == 1) ? acc.y
                          : (u == 2) ? acc.z : acc.w;
                int   j   = j0 + jg + u;
                float t   = sqt + s_csq[jg + u];
                float d   = fmaf(dot, -2.0f, t);  // one final rounding
                unsigned long long key =
                    ((unsigned long long)__float_as_uint(d) << 32) |
                    (unsigned int)j;
                bool q = (j != tgt) && (key < curMax);
                if (__any_sync(0xffffffffu, q)) {
                    if (q) {
                        top[curSlot] = key;       // replace current max
                        unsigned long long mv = 0ull;
                        int ms = 0;
#pragma unroll
                        for (int k = 0; k < KNN; k++) {
                            unsigned long long v = top[k];
                            if (v > mv) { mv = v; ms = k; }
                        }
                        curMax = mv; curSlot = ms;
                    }
                }
            }
        }
    }

    // Emit in ascending (distance, index) order via repeated min-extraction.
    // Output dtype is float32: write indices as floats (exact up to 2^24).
    const int base0 = ((0 * BATCH + b) * NPTS + tgt) * KNN;
    const int base1 = ((1 * BATCH + b) * NPTS + tgt) * KNN;
    const float ftgt = (float)tgt;
#pragma unroll
    for (int p = 0; p < KNN; p++) {
        unsigned long long mv = ~0ull;
        int ms = 0;
#pragma unroll
        for (int k = 0; k < KNN; k++) {
            unsigned long long v = top[k];
            if (v < mv) { mv = v; ms = k; }
        }
        out[base0 + p] = (float)(int)(unsigned int)(mv & 0xffffffffu);
        out[base1 + p] = ftgt;
        top[ms] = ~0ull;
    }
}

// ---------------------------------------------------------------------------
extern "C" void kernel_launch(void* const* d_in, const int* in_sizes, int n_in,
                              void* d_out, int out_size) {
    (void)in_sizes; (void)n_in; (void)out_size;
    const float* x = (const float*)d_in[0];
    float* out = (float*)d_out;

    dim3 grid(NPTS / TM, BATCH);
    knn_all<<<grid, TM>>>(x, out);
}

// round 4
// speedup vs baseline: 1.4603x; 1.4603x over previous
#include <cuda_runtime.h>

// Fixed problem shape
#define BATCH 8
#define CDIM  64
#define NPTS  4096
#define KNN   20
#define TM    128   // targets per block == threads per block
#define TC    64    // candidate tile size

// ---------------------------------------------------------------------------
// One kernel. One thread = one target point.
//  - Target features in registers (64 floats).
//  - Candidate tile (64 pts x 64 ch, channel-major) in SMEM; dot products via
//    uniform float4 broadcast loads (1 LDS.128 per 4 FFMA4).
//  - Top-K: sorted (dist,idx) arrays held ENTIRELY IN REGISTERS with static
//    indexing only (fully unrolled stable bubble insert). Strict-< swaps give
//    lax.top_k's exact tie rule (equal distance -> lower index first).
//  - d2 = fma(dot, -2, sq_t + sq_j): same rounding as the reference's
//    sq[:,:,None] + sq[:,None,:] - 2*einsum. Accumulation order identical to
//    the round-3 kernel (verified rel_err 9.3e-4 < 1e-3).
//  - Output dtype float32: indices written as floats (exact).
// ---------------------------------------------------------------------------
__global__ void __launch_bounds__(TM) knn_all(const float* __restrict__ x,
                                              float* __restrict__ out) {
    __shared__ __align__(16) float sf[CDIM * TC];  // tile, channel-major rows
    __shared__ float s_csq[TC];                    // candidate squared norms

    const int b   = blockIdx.y;
    const int tid = threadIdx.x;
    const int tgt = blockIdx.x * TM + tid;
    const float* xb = x + b * CDIM * NPTS;

    // Target features -> registers; target squared norm.
    float tq[CDIM];
    float sqt = 0.f;
#pragma unroll
    for (int c = 0; c < CDIM; c++) {
        tq[c] = xb[c * NPTS + tgt];
        sqt = fmaf(tq[c], tq[c], sqt);
    }

    // Register-resident sorted top-K (ascending distance; ties: lower index).
    float dist[KNN];
    int   idx[KNN];
#pragma unroll
    for (int k = 0; k < KNN; k++) { dist[k] = __int_as_float(0x7f800000); idx[k] = 0; }

    const int cand  = tid & (TC - 1);   // candidate column this thread stages
    const int chalf = tid >> 6;         // channel parity (TM = 2*TC)

    for (int j0 = 0; j0 < NPTS; j0 += TC) {
        __syncthreads();                // prior tile fully consumed
        // Stage candidate tile: thread handles 32 channels of one candidate.
        for (int c = chalf; c < CDIM; c += 2)
            sf[c * TC + cand] = xb[c * NPTS + j0 + cand];
        __syncthreads();
        // Candidate squared norms from the staged tile.
        if (tid < TC) {
            float s = 0.f;
#pragma unroll
            for (int c = 0; c < CDIM; c++) {
                float v = sf[c * TC + tid];
                s = fmaf(v, v, s);
            }
            s_csq[tid] = s;
        }
        __syncthreads();

        for (int jg = 0; jg < TC; jg += 4) {
            float4 acc = make_float4(0.f, 0.f, 0.f, 0.f);
            const float4* row4 = reinterpret_cast<const float4*>(sf) + (jg >> 2);
#pragma unroll
            for (int c = 0; c < CDIM; c++) {
                float4 cv = row4[c * (TC / 4)];   // uniform broadcast LDS.128
                float a = tq[c];
                acc.x = fmaf(a, cv.x, acc.x);
                acc.y = fmaf(a, cv.y, acc.y);
                acc.z = fmaf(a, cv.z, acc.z);
                acc.w = fmaf(a, cv.w, acc.w);
            }
#pragma unroll
            for (int u = 0; u < 4; u++) {
                float dot = (u == 0) ? acc.x : (u == 1) ? acc.y
                          : (u == 2) ? acc.z : acc.w;
                int   j   = j0 + jg + u;
                float t   = sqt + s_csq[jg + u];
                float d   = fmaf(dot, -2.0f, t);  // one final rounding
                if (j != tgt && d < dist[KNN - 1]) {
                    // Place at bottom, stable bubble toward front.
                    dist[KNN - 1] = d;
                    idx[KNN - 1]  = j;
#pragma unroll
                    for (int k = KNN - 1; k > 0; k--) {
                        bool sw = dist[k] < dist[k - 1];   // strict: stable ties
                        float da = dist[k - 1]; int ia = idx[k - 1];
                        float db = dist[k];     int ib = idx[k];
                        dist[k - 1] = sw ? db : da; idx[k - 1] = sw ? ib : ia;
                        dist[k]     = sw ? da : db; idx[k]     = sw ? ia : ib;
                    }
                }
            }
        }
    }

    // Already sorted ascending (distance, index): emit directly.
    const int base0 = ((0 * BATCH + b) * NPTS + tgt) * KNN;
    const int base1 = ((1 * BATCH + b) * NPTS + tgt) * KNN;
    const float ftgt = (float)tgt;
#pragma unroll
    for (int p = 0; p < KNN; p++) {
        out[base0 + p] = (float)idx[p];
        out[base1 + p] = ftgt;
    }
}

// ---------------------------------------------------------------------------
extern "C" void kernel_launch(void* const* d_in, const int* in_sizes, int n_in,
                              void* d_out, int out_size) {
    (void)in_sizes; (void)n_in; (void)out_size;
    const float* x = (const float*)d_in[0];
    float* out = (float*)d_out;

    dim3 grid(NPTS / TM, BATCH);
    knn_all<<<grid, TM>>>(x, out);
}